// round 7
// baseline (speedup 1.0000x reference)
#include <cuda_runtime.h>

// ---------------------------------------------------------------------------
// Fused 3-layer tanh RNN + FC head.  B=8192, T=80, D=32, H=64.
// CTA = 64 batch, 256 threads (8 warps), grid = 128.
//
// v2 tiling: each warp owns 8 j-columns x all 64 batches.
//   lane = (bg, jg):  bg = lane&7 (8 b-groups), jg = lane>>3 (4 j-groups of 2 j)
//   lane batches: bA = bg*4 (4 consecutive) and bB = 32 + bg*4 (4 consecutive)
//   -> each h LDS.128 covers one contiguous 128B row segment (1 wavefront)
// Weights stored j-duplicated in smem as u64 {w,w}: one broadcast LDS.128
// per lane per k yields both dup'd weight pairs (1 wavefront, no MOVs).
// Per warp per k: 3 LDS + 8 FMA2.  smem 24 wf/SM/k vs FMA floor 32 cyc/SMSP/k.
// ---------------------------------------------------------------------------

typedef unsigned long long u64;

#define B_TOT    8192
#define T_STEPS  80
#define D_IN     32
#define HDIM     64
#define BT       64
#define NTHREADS 256

// ---- smem layout -----------------------------------------------------------
// u64 region (dup'd weights + dup'd biases), then float region.
#define U_WHH0 0
#define U_WIH1 4096
#define U_WHH1 8192
#define U_WIH2 12288
#define U_WHH2 16384
#define U_BSD  20480              // 3*64 dup'd combined biases
#define U_END  (U_BSD + 192)      // 20672 u64 = 165376 bytes

#define F_BASE  (U_END * 2)       // float index of float region
#define F_X     (F_BASE)                    // 32 x 64
#define F_H0    (F_X    + D_IN * HDIM)      // 64 x 64
#define F_H1    (F_H0   + HDIM * HDIM)
#define F_H2    (F_H1   + HDIM * HDIM)
#define F_WIH0  (F_H2   + HDIM * HDIM)      // 32 x 64 (scalar, k-major)
#define F_WFC   (F_WIH0 + D_IN * HDIM)
#define F_BFC   (F_WFC  + HDIM)
#define SMEM_FLOATS (F_BFC + 1)
#define SMEM_BYTES  (SMEM_FLOATS * 4)       // 231172 < 232448 (227KB limit)

// ---- packed fp32x2 helpers -------------------------------------------------
__device__ __forceinline__ u64 dup2f(float v) {
    u64 r;
    asm("mov.b64 %0, {%1, %1};" : "=l"(r) : "f"(v));
    return r;
}
__device__ __forceinline__ float2 unpack2(u64 v) {
    float2 r;
    asm("mov.b64 {%0, %1}, %2;" : "=f"(r.x), "=f"(r.y) : "l"(v));
    return r;
}
#define FMA2(accv, av, bv) \
    asm("fma.rn.f32x2 %0, %1, %2, %0;" : "+l"(accv) : "l"(av), "l"(bv))

// ---- K-reduction with dup'd weights ---------------------------------------
// acc[i][jj]: i = b-pair (0,1 from bA; 2,3 from bB), jj = j0 / j0+1
template <int K>
__device__ __forceinline__ void accum_dup(const float* __restrict__ inT,
                                          const u64* __restrict__ WD,
                                          int bA, int bB, int j0,
                                          u64 acc[4][2]) {
#pragma unroll 8
    for (int k = 0; k < K; ++k) {
        ulonglong2 hA = *reinterpret_cast<const ulonglong2*>(inT + k * HDIM + bA);
        ulonglong2 hB = *reinterpret_cast<const ulonglong2*>(inT + k * HDIM + bB);
        ulonglong2 w  = *reinterpret_cast<const ulonglong2*>(WD + k * HDIM + j0);
        FMA2(acc[0][0], hA.x, w.x); FMA2(acc[0][1], hA.x, w.y);
        FMA2(acc[1][0], hA.y, w.x); FMA2(acc[1][1], hA.y, w.y);
        FMA2(acc[2][0], hB.x, w.x); FMA2(acc[2][1], hB.x, w.y);
        FMA2(acc[3][0], hB.y, w.x); FMA2(acc[3][1], hB.y, w.y);
    }
}

// ---- K-reduction with scalar weights (Wih0 only, 32 k-rows) ----------------
__device__ __forceinline__ void accum_ih0(const float* __restrict__ xT,
                                          const float* __restrict__ W,
                                          int bA, int bB, int j0,
                                          u64 acc[4][2]) {
#pragma unroll 8
    for (int k = 0; k < D_IN; ++k) {
        ulonglong2 hA = *reinterpret_cast<const ulonglong2*>(xT + k * HDIM + bA);
        ulonglong2 hB = *reinterpret_cast<const ulonglong2*>(xT + k * HDIM + bB);
        float2 wv = *reinterpret_cast<const float2*>(W + k * HDIM + j0);
        u64 w0 = dup2f(wv.x);
        u64 w1 = dup2f(wv.y);
        FMA2(acc[0][0], hA.x, w0); FMA2(acc[0][1], hA.x, w1);
        FMA2(acc[1][0], hA.y, w0); FMA2(acc[1][1], hA.y, w1);
        FMA2(acc[2][0], hB.x, w0); FMA2(acc[2][1], hB.x, w1);
        FMA2(acc[3][0], hB.y, w0); FMA2(acc[3][1], hB.y, w1);
    }
}

// ---- tanh epilogue: write lane's 2 j-rows (4+4 batches each) ---------------
__device__ __forceinline__ void epilogue(float* __restrict__ hT,
                                         int bA, int bB, int j0,
                                         u64 acc[4][2]) {
#pragma unroll
    for (int jj = 0; jj < 2; ++jj) {
        float2 a0 = unpack2(acc[0][jj]), a1 = unpack2(acc[1][jj]);
        float2 a2 = unpack2(acc[2][jj]), a3 = unpack2(acc[3][jj]);
        float* row = hT + (j0 + jj) * HDIM;
        *reinterpret_cast<float4*>(row + bA) =
            make_float4(tanhf(a0.x), tanhf(a0.y), tanhf(a1.x), tanhf(a1.y));
        *reinterpret_cast<float4*>(row + bB) =
            make_float4(tanhf(a2.x), tanhf(a2.y), tanhf(a3.x), tanhf(a3.y));
    }
}

// ---- setup: transpose + duplicate a [64][64] weight into WD[k][j] ----------
__device__ __forceinline__ void load_wdup(const float* __restrict__ W,
                                          u64* __restrict__ WD, int tid) {
    for (int idx = tid; idx < HDIM * HDIM; idx += NTHREADS) {
        int k = idx >> 6, j = idx & 63;
        WD[idx] = dup2f(W[j * HDIM + k]);    // idx = k*64 + j
    }
}

__global__ void __launch_bounds__(NTHREADS, 1)
rnn_fused_v2(const float* __restrict__ x,
             const float* __restrict__ Wih0, const float* __restrict__ Whh0,
             const float* __restrict__ bih0, const float* __restrict__ bhh0,
             const float* __restrict__ Wih1, const float* __restrict__ Whh1,
             const float* __restrict__ bih1, const float* __restrict__ bhh1,
             const float* __restrict__ Wih2, const float* __restrict__ Whh2,
             const float* __restrict__ bih2, const float* __restrict__ bhh2,
             const float* __restrict__ Wfc,  const float* __restrict__ bfc,
             float* __restrict__ out) {
    extern __shared__ __align__(16) float smem[];
    u64* smemu = reinterpret_cast<u64*>(smem);
    const int tid   = threadIdx.x;
    const int bbase = blockIdx.x * BT;

    // ---- one-time setup -----------------------------------------------------
    load_wdup(Whh0, smemu + U_WHH0, tid);
    load_wdup(Whh1, smemu + U_WHH1, tid);
    load_wdup(Whh2, smemu + U_WHH2, tid);
    load_wdup(Wih1, smemu + U_WIH1, tid);
    load_wdup(Wih2, smemu + U_WIH2, tid);
    // Wih0: scalar k-major transpose [32][64]
    for (int idx = tid; idx < HDIM * D_IN; idx += NTHREADS) {
        int k = idx >> 6, j = idx & 63;                  // idx = k*64 + j
        smem[F_WIH0 + idx] = Wih0[j * D_IN + k];
    }
    // dup'd combined biases
    if (tid < 3 * HDIM) {
        int l = tid >> 6, j = tid & 63;
        const float* bi = (l == 0) ? bih0 : (l == 1) ? bih1 : bih2;
        const float* bh = (l == 0) ? bhh0 : (l == 1) ? bhh1 : bhh2;
        smemu[U_BSD + tid] = dup2f(bi[j] + bh[j]);
    }
    if (tid < HDIM) smem[F_WFC + tid] = Wfc[tid];
    if (tid == 0)   smem[F_BFC] = bfc[0];
    // zero hidden states
    for (int i = tid; i < 3 * HDIM * HDIM; i += NTHREADS) smem[F_H0 + i] = 0.0f;

    // ---- x prefetch: thread owns 8 consecutive floats of one (b,t) row ------
    const int xb = tid >> 2;            // local batch 0..63
    const int xd = (tid & 3) * 8;       // d offset 0,8,16,24
    const float* xp = x + (size_t)(bbase + xb) * (T_STEPS * D_IN) + xd;
    float4 xr0 = *reinterpret_cast<const float4*>(xp);
    float4 xr1 = *reinterpret_cast<const float4*>(xp + 4);

    __syncthreads();

    const int lane = tid & 31;
    const int warp = tid >> 5;
    const int bg   = lane & 7;
    const int jg   = lane >> 3;
    const int bA   = bg * 4;            // batches bA..bA+3
    const int bB   = 32 + bg * 4;       // batches bB..bB+3
    const int j0   = warp * 8 + jg * 2; // lane's j pair

    const u64* BSD = smemu + U_BSD;

    for (int t = 0; t < T_STEPS; ++t) {
        // stage x_t (transposed xT[d][b]); prefetch x_{t+1}
        float* xc = smem + F_X + xb;
        xc[(xd + 0) * HDIM] = xr0.x; xc[(xd + 1) * HDIM] = xr0.y;
        xc[(xd + 2) * HDIM] = xr0.z; xc[(xd + 3) * HDIM] = xr0.w;
        xc[(xd + 4) * HDIM] = xr1.x; xc[(xd + 5) * HDIM] = xr1.y;
        xc[(xd + 6) * HDIM] = xr1.z; xc[(xd + 7) * HDIM] = xr1.w;
        if (t + 1 < T_STEPS) {
            xr0 = *reinterpret_cast<const float4*>(xp + (t + 1) * D_IN);
            xr1 = *reinterpret_cast<const float4*>(xp + (t + 1) * D_IN + 4);
        }
        __syncthreads();

        u64 acc[4][2];

        // ---- layer 0: h0 = tanh(b0 + Wih0 x + Whh0 h0) ----
        {
            ulonglong2 b2 = *reinterpret_cast<const ulonglong2*>(BSD + j0);
#pragma unroll
            for (int i = 0; i < 4; ++i) { acc[i][0] = b2.x; acc[i][1] = b2.y; }
            accum_ih0(smem + F_X, smem + F_WIH0, bA, bB, j0, acc);
            accum_dup<HDIM>(smem + F_H0, smemu + U_WHH0, bA, bB, j0, acc);
            __syncthreads();
            epilogue(smem + F_H0, bA, bB, j0, acc);
            __syncthreads();
        }
        // ---- layer 1: h1 = tanh(b1 + Wih1 h0 + Whh1 h1) ----
        {
            ulonglong2 b2 = *reinterpret_cast<const ulonglong2*>(BSD + HDIM + j0);
#pragma unroll
            for (int i = 0; i < 4; ++i) { acc[i][0] = b2.x; acc[i][1] = b2.y; }
            accum_dup<HDIM>(smem + F_H0, smemu + U_WIH1, bA, bB, j0, acc);
            accum_dup<HDIM>(smem + F_H1, smemu + U_WHH1, bA, bB, j0, acc);
            __syncthreads();
            epilogue(smem + F_H1, bA, bB, j0, acc);
            __syncthreads();
        }
        // ---- layer 2: h2 = tanh(b2 + Wih2 h1 + Whh2 h2) ----
        {
            ulonglong2 b2 = *reinterpret_cast<const ulonglong2*>(BSD + 2 * HDIM + j0);
#pragma unroll
            for (int i = 0; i < 4; ++i) { acc[i][0] = b2.x; acc[i][1] = b2.y; }
            accum_dup<HDIM>(smem + F_H1, smemu + U_WIH2, bA, bB, j0, acc);
            accum_dup<HDIM>(smem + F_H2, smemu + U_WHH2, bA, bB, j0, acc);
            __syncthreads();
            epilogue(smem + F_H2, bA, bB, j0, acc);
            __syncthreads();
        }
    }

    // ---- FC head: out[b] = h2_last[b] . Wfc + bfc ---------------------------
    if (tid < BT) {
        float s = smem[F_BFC];
        const float* h2 = smem + F_H2;
        const float* wf = smem + F_WFC;
#pragma unroll
        for (int j = 0; j < HDIM; ++j) s += h2[j * HDIM + tid] * wf[j];
        out[bbase + tid] = s;
    }
}

extern "C" void kernel_launch(void* const* d_in, const int* in_sizes, int n_in,
                              void* d_out, int out_size) {
    (void)in_sizes; (void)n_in; (void)out_size;
    cudaFuncSetAttribute(rnn_fused_v2,
                         cudaFuncAttributeMaxDynamicSharedMemorySize,
                         SMEM_BYTES);
    rnn_fused_v2<<<B_TOT / BT, NTHREADS, SMEM_BYTES>>>(
        (const float*)d_in[0],
        (const float*)d_in[1],  (const float*)d_in[2],
        (const float*)d_in[3],  (const float*)d_in[4],
        (const float*)d_in[5],  (const float*)d_in[6],
        (const float*)d_in[7],  (const float*)d_in[8],
        (const float*)d_in[9],  (const float*)d_in[10],
        (const float*)d_in[11], (const float*)d_in[12],
        (const float*)d_in[13], (const float*)d_in[14],
        (float*)d_out);
}

// round 8
// speedup vs baseline: 1.6239x; 1.6239x over previous
#include <cuda_runtime.h>

// ---------------------------------------------------------------------------
// Fused 3-layer tanh RNN + FC head, single persistent time loop per CTA.
//   B=8192, T=80, D=32, H=64.  CTA = 64 batch elems, 256 threads, grid=128.
//
// v3 = v1 (835us baseline) with all hot-loop __syncthreads removed.
// Key insight: the time loop is WARP-PRIVATE in the batch dim — warp w owns
// batch columns [w*8, w*8+8); it writes h only at those columns and reads h
// only at those columns (both the Whh recurrence and the next layer's Wih
// input). x staging is also warp-private. Only __syncwarp is needed around
// each epilogue; warps free-run across t, hiding LDS latency in each other's
// FMA streams instead of stalling in lockstep.
// ---------------------------------------------------------------------------

#define B_TOT    8192
#define T_STEPS  80
#define D_IN     32
#define HDIM     64
#define BT       64          // batch tile per CTA
#define NTHREADS 256
#define P        68          // smem row pitch in floats

// smem layout offsets (in floats)
#define OFF_X    0
#define OFF_H0   (OFF_X    + D_IN * P)
#define OFF_H1   (OFF_H0   + HDIM * P)
#define OFF_H2   (OFF_H1   + HDIM * P)
#define OFF_WIH0 (OFF_H2   + HDIM * P)
#define OFF_WHH0 (OFF_WIH0 + D_IN * P)
#define OFF_WIH1 (OFF_WHH0 + HDIM * P)
#define OFF_WHH1 (OFF_WIH1 + HDIM * P)
#define OFF_WIH2 (OFF_WHH1 + HDIM * P)
#define OFF_WHH2 (OFF_WIH2 + HDIM * P)
#define OFF_BS   (OFF_WHH2 + HDIM * P)   // 3 x 64 combined biases
#define OFF_WFC  (OFF_BS   + 3 * HDIM)
#define OFF_BFC  (OFF_WFC  + HDIM)
#define SMEM_FLOATS (OFF_BFC + 1)

// ---- packed fp32x2 helpers --------------------------------------------------
__device__ __forceinline__ unsigned long long dup2(float v) {
    unsigned long long r;
    asm("mov.b64 %0, {%1, %1};" : "=l"(r) : "f"(v));
    return r;
}
__device__ __forceinline__ float2 unpack2(unsigned long long v) {
    float2 r;
    asm("mov.b64 {%0, %1}, %2;" : "=f"(r.x), "=f"(r.y) : "l"(v));
    return r;
}
#define FMA2(accv, av, bv) \
    asm("fma.rn.f32x2 %0, %1, %2, %0;" : "+l"(accv) : "l"(av), "l"(bv))

// ---- outer-product accumulate over K: acc[b-pair][j] += inT[k][b] * WT[k][j]
template <int K>
__device__ __forceinline__ void accum(const float* __restrict__ inT,
                                      const float* __restrict__ WT,
                                      int b0, int j0,
                                      unsigned long long acc[4][2]) {
#pragma unroll 16
    for (int k = 0; k < K; ++k) {
        double2 ha = *reinterpret_cast<const double2*>(inT + k * P + b0);
        double2 hb = *reinterpret_cast<const double2*>(inT + k * P + b0 + 4);
        float2 wv = *reinterpret_cast<const float2*>(WT + k * P + j0);
        unsigned long long w0 = dup2(wv.x);
        unsigned long long w1 = dup2(wv.y);
        unsigned long long h01 = __double_as_longlong(ha.x);
        unsigned long long h23 = __double_as_longlong(ha.y);
        unsigned long long h45 = __double_as_longlong(hb.x);
        unsigned long long h67 = __double_as_longlong(hb.y);
        FMA2(acc[0][0], h01, w0); FMA2(acc[0][1], h01, w1);
        FMA2(acc[1][0], h23, w0); FMA2(acc[1][1], h23, w1);
        FMA2(acc[2][0], h45, w0); FMA2(acc[2][1], h45, w1);
        FMA2(acc[3][0], h67, w0); FMA2(acc[3][1], h67, w1);
    }
}

// ---- one RNN layer step: h_out = tanh(bias + WinT^T in + WhhT^T h_out_prev)
// Warp-private: all smem traffic touches only this warp's batch columns.
template <int KIN>
__device__ __forceinline__ void layer_step(const float* __restrict__ inT,
                                           const float* __restrict__ WinT,
                                           float* __restrict__ hT,
                                           const float* __restrict__ WhhT,
                                           const float* __restrict__ bs,
                                           int b0, int j0) {
    unsigned long long acc[4][2];
    float2 bv = *reinterpret_cast<const float2*>(bs + j0);
#pragma unroll
    for (int i = 0; i < 4; ++i) { acc[i][0] = dup2(bv.x); acc[i][1] = dup2(bv.y); }

    accum<KIN>(inT, WinT, b0, j0, acc);   // input projection
    accum<HDIM>(hT,  WhhT, b0, j0, acc);  // recurrent part (reads old h)

    __syncwarp();  // all lanes' reads of old hT columns done before overwrite

    float2 p0 = unpack2(acc[0][0]), p1 = unpack2(acc[1][0]);
    float2 p2 = unpack2(acc[2][0]), p3 = unpack2(acc[3][0]);
    float4 v0 = make_float4(tanhf(p0.x), tanhf(p0.y), tanhf(p1.x), tanhf(p1.y));
    float4 v1 = make_float4(tanhf(p2.x), tanhf(p2.y), tanhf(p3.x), tanhf(p3.y));
    *reinterpret_cast<float4*>(hT + j0 * P + b0)     = v0;
    *reinterpret_cast<float4*>(hT + j0 * P + b0 + 4) = v1;

    float2 q0 = unpack2(acc[0][1]), q1 = unpack2(acc[1][1]);
    float2 q2 = unpack2(acc[2][1]), q3 = unpack2(acc[3][1]);
    float4 u0 = make_float4(tanhf(q0.x), tanhf(q0.y), tanhf(q1.x), tanhf(q1.y));
    float4 u1 = make_float4(tanhf(q2.x), tanhf(q2.y), tanhf(q3.x), tanhf(q3.y));
    *reinterpret_cast<float4*>(hT + (j0 + 1) * P + b0)     = u0;
    *reinterpret_cast<float4*>(hT + (j0 + 1) * P + b0 + 4) = u1;

    __syncwarp();  // new h visible to all lanes of this warp
}

// ---- transpose weight [64][K] row-major -> WT[k*P + j] ----------------------
__device__ __forceinline__ void load_wT(const float* __restrict__ W,
                                        float* __restrict__ WT, int K, int tid) {
    for (int idx = tid; idx < HDIM * K; idx += NTHREADS) {
        int j = idx / K;
        int k = idx - j * K;
        WT[k * P + j] = W[idx];
    }
}

__global__ void __launch_bounds__(NTHREADS, 1)
rnn_fused_v3(const float* __restrict__ x,
             const float* __restrict__ Wih0, const float* __restrict__ Whh0,
             const float* __restrict__ bih0, const float* __restrict__ bhh0,
             const float* __restrict__ Wih1, const float* __restrict__ Whh1,
             const float* __restrict__ bih1, const float* __restrict__ bhh1,
             const float* __restrict__ Wih2, const float* __restrict__ Whh2,
             const float* __restrict__ bih2, const float* __restrict__ bhh2,
             const float* __restrict__ Wfc,  const float* __restrict__ bfc,
             float* __restrict__ out) {
    extern __shared__ float smem[];
    const int tid   = threadIdx.x;
    const int bbase = blockIdx.x * BT;

    // ---- one-time setup: weights (transposed), biases, zero hidden states
    load_wT(Wih0, smem + OFF_WIH0, D_IN, tid);
    load_wT(Whh0, smem + OFF_WHH0, HDIM, tid);
    load_wT(Wih1, smem + OFF_WIH1, HDIM, tid);
    load_wT(Whh1, smem + OFF_WHH1, HDIM, tid);
    load_wT(Wih2, smem + OFF_WIH2, HDIM, tid);
    load_wT(Whh2, smem + OFF_WHH2, HDIM, tid);
    if (tid < 3 * HDIM) {
        int l = tid >> 6, j = tid & 63;
        const float* bi = (l == 0) ? bih0 : (l == 1) ? bih1 : bih2;
        const float* bh = (l == 0) ? bhh0 : (l == 1) ? bhh1 : bhh2;
        smem[OFF_BS + tid] = bi[j] + bh[j];
    }
    if (tid < HDIM) smem[OFF_WFC + tid] = Wfc[tid];
    if (tid == 0)   smem[OFF_BFC] = bfc[0];
    for (int i = tid; i < 3 * HDIM * P; i += NTHREADS) smem[OFF_H0 + i] = 0.0f;

    // ---- x prefetch: each thread owns 8 consecutive floats of one row
    // (warp-private: warp w's threads cover exactly batch columns w*8..w*8+7)
    const int xb = tid >> 2;            // local batch index 0..63
    const int xd = (tid & 3) * 8;       // d offset 0,8,16,24
    const float* xp = x + (size_t)(bbase + xb) * (T_STEPS * D_IN) + xd;
    float4 xr0 = *reinterpret_cast<const float4*>(xp);
    float4 xr1 = *reinterpret_cast<const float4*>(xp + 4);

    __syncthreads();   // weights/biases/zeroed state visible to all warps

    const int lane = tid & 31;
    const int b0   = (tid >> 5) * 8;    // warp's batch sub-tile
    const int j0   = lane * 2;          // lane's hidden-unit pair

    for (int t = 0; t < T_STEPS; ++t) {
        // stage x_t into smem (transposed: xT[d][b]); prefetch x_{t+1}
        float* xc = smem + OFF_X + xb;
        xc[(xd + 0) * P] = xr0.x; xc[(xd + 1) * P] = xr0.y;
        xc[(xd + 2) * P] = xr0.z; xc[(xd + 3) * P] = xr0.w;
        xc[(xd + 4) * P] = xr1.x; xc[(xd + 5) * P] = xr1.y;
        xc[(xd + 6) * P] = xr1.z; xc[(xd + 7) * P] = xr1.w;
        if (t + 1 < T_STEPS) {
            xr0 = *reinterpret_cast<const float4*>(xp + (t + 1) * D_IN);
            xr1 = *reinterpret_cast<const float4*>(xp + (t + 1) * D_IN + 4);
        }
        __syncwarp();   // warp's x columns staged

        layer_step<D_IN>(smem + OFF_X,  smem + OFF_WIH0, smem + OFF_H0,
                         smem + OFF_WHH0, smem + OFF_BS,            b0, j0);
        layer_step<HDIM>(smem + OFF_H0, smem + OFF_WIH1, smem + OFF_H1,
                         smem + OFF_WHH1, smem + OFF_BS + HDIM,     b0, j0);
        layer_step<HDIM>(smem + OFF_H1, smem + OFF_WIH2, smem + OFF_H2,
                         smem + OFF_WHH2, smem + OFF_BS + 2 * HDIM, b0, j0);
    }

    __syncthreads();   // FC head reads h2 across warp boundaries

    // ---- FC head: out[b] = h2_last[b] . Wfc + bfc
    if (tid < BT) {
        float s = smem[OFF_BFC];
        const float* h2 = smem + OFF_H2;
        const float* wf = smem + OFF_WFC;
#pragma unroll
        for (int j = 0; j < HDIM; ++j) s += h2[j * P + tid] * wf[j];
        out[bbase + tid] = s;
    }
}

extern "C" void kernel_launch(void* const* d_in, const int* in_sizes, int n_in,
                              void* d_out, int out_size) {
    (void)in_sizes; (void)n_in; (void)out_size;
    const size_t smem_bytes = SMEM_FLOATS * sizeof(float);
    cudaFuncSetAttribute(rnn_fused_v3,
                         cudaFuncAttributeMaxDynamicSharedMemorySize,
                         (int)smem_bytes);
    rnn_fused_v3<<<B_TOT / BT, NTHREADS, smem_bytes>>>(
        (const float*)d_in[0],
        (const float*)d_in[1],  (const float*)d_in[2],
        (const float*)d_in[3],  (const float*)d_in[4],
        (const float*)d_in[5],  (const float*)d_in[6],
        (const float*)d_in[7],  (const float*)d_in[8],
        (const float*)d_in[9],  (const float*)d_in[10],
        (const float*)d_in[11], (const float*)d_in[12],
        (const float*)d_in[13], (const float*)d_in[14],
        (float*)d_out);
}